// round 16
// baseline (speedup 1.0000x reference)
#include <cuda_runtime.h>

// Census loss, pair-symmetric, f32x2-packed, 4 adjacent pixels/thread
// (two pair-groups sharing neighbor loads via dual shifted float4 layouts).
// t = 1 - 0.1*rc, rc = 1/(0.1+e^2), e = cx-cy, c = d*rsqrt(7.29+d^2),
// d = g3(b)-g3(a), g3 = r+g+b (/3 folded into 0.81*9=7.29).
// Interior thread (96 pairs, weight 2): res = 192 - 0.2*sum(rc).
// A[k] = {gx0,gx1,gy0,gy1} for pixel pair (2k-4,2k-3)+col0; B = A shifted +1 px.
// Every dx neighbor pair is one aligned ld.shared.v2.b64.

#define IMG   256
#define IMG2  65536
#define PITCH 20        // float4 per row (40 px: 4 left halo + 32 + 4)
#define SROWS 22        // 16 tile rows + 6 halo
#define NEL   440       // SROWS * PITCH

typedef unsigned long long ull;

__device__ __forceinline__ float frsqrt_a(float x){ float r; asm("rsqrt.approx.f32 %0, %1;" : "=f"(r) : "f"(x)); return r; }
__device__ __forceinline__ float frcp_a  (float x){ float r; asm("rcp.approx.f32 %0, %1;"   : "=f"(r) : "f"(x)); return r; }

__device__ __forceinline__ ull pk(float lo, float hi){ ull r; asm("mov.b64 %0, {%1, %2};" : "=l"(r) : "f"(lo), "f"(hi)); return r; }
__device__ __forceinline__ float2 upk(ull v){ float2 f; asm("mov.b64 {%0, %1}, %2;" : "=f"(f.x), "=f"(f.y) : "l"(v)); return f; }
__device__ __forceinline__ ull fma2(ull a, ull b, ull c){ ull r; asm("fma.rn.f32x2 %0, %1, %2, %3;" : "=l"(r) : "l"(a), "l"(b), "l"(c)); return r; }
__device__ __forceinline__ ull mul2(ull a, ull b){ ull r; asm("mul.rn.f32x2 %0, %1, %2;" : "=l"(r) : "l"(a), "l"(b)); return r; }
__device__ __forceinline__ ull sub2(ull a, ull b){ ull r; asm("sub.rn.f32x2 %0, %1, %2;" : "=l"(r) : "l"(a), "l"(b)); return r; }

// one 128-bit shared load -> x-image pair (a) and y-image pair (b)
__device__ __forceinline__ void lds128(const float4* p, ull& a, ull& b){
    asm("ld.shared.v2.b64 {%0, %1}, [%2];"
        : "=l"(a), "=l"(b) : "l"(__cvta_generic_to_shared(p)));
}

// packed rc = 1/(0.1+e^2) for two pixel-pairs (fused rational, 3 MUFU/pair)
__device__ __forceinline__ float2 pair_rc2(ull nbx, ull nby, ull cenx, ull ceny,
                                           ull C729, ull C01)
{
    ull dX = sub2(nbx, cenx);
    ull dY = sub2(nby, ceny);
    ull aX = fma2(dX, dX, C729);
    ull aY = fma2(dY, dY, C729);
    float2 a = upk(aX);
    ull rX = pk(frsqrt_a(a.x), frsqrt_a(a.y));
    float2 b = upk(aY);
    ull rY = pk(frsqrt_a(b.x), frsqrt_a(b.y));
    ull cx = mul2(dX, rX);
    ull cy = mul2(dY, rY);
    ull e  = sub2(cx, cy);
    ull dn = fma2(e, e, C01);
    float2 d = upk(dn);
    float2 rc;
    rc.x = frcp_a(d.x);
    rc.y = frcp_a(d.y);
    return rc;
}

template<bool BORDER>
__device__ __forceinline__ float census_body(const float4* __restrict__ Ab,
                                             const float4* __restrict__ Bb,
                                             int r, int C)
{
    const ull C729 = pk(7.29f, 7.29f);
    const ull C01  = pk(0.1f, 0.1f);

    float vrow[4], vcw[10];
    float va0 = 0.f, va1 = 0.f, va2 = 0.f, va3 = 0.f;
    if (BORDER) {
#pragma unroll
        for (int d = 0; d < 4; d++) vrow[d] = ((unsigned)(r + d - 3) < 250u) ? 1.f : 0.f;   // valid(row r+d)
#pragma unroll
        for (int k = 0; k < 10; k++) vcw[k] = ((unsigned)(C + k - 6) < 250u) ? 1.f : 0.f;   // valid(col C+k-3)
        va0 = vrow[0] * vcw[3];
        va1 = vrow[0] * vcw[4];
        va2 = vrow[0] * vcw[5];
        va3 = vrow[0] * vcw[6];
    }

    float accA = 0.f, accB = 0.f, accC = 0.f, accD = 0.f, accw = 0.f;

    ull cen0x, cen0y, cen1x, cen1y;
    lds128(Ab + 2, cen0x, cen0y);    // pixels C, C+1
    lds128(Ab + 3, cen1x, cen1y);    // pixels C+2, C+3

    // ---- dy = 0: right-half offsets (dx = 1,2,3) for both groups ----
    {
        ull b2x, b2y, b3x, b3y, a4x, a4y, b4x, b4y;
        lds128(Bb + 2, b2x, b2y);
        lds128(Bb + 3, b3x, b3y);
        lds128(Ab + 4, a4x, a4y);
        lds128(Bb + 4, b4x, b4y);

        float2 rc;
        // group 0: dx=1 (B[2]), dx=2 (A[3]=cen1 regs), dx=3 (B[3])
        rc = pair_rc2(b2x, b2y, cen0x, cen0y, C729, C01);
        if (BORDER) { float w0 = fmaf(vrow[0], vcw[4], va0), w1 = fmaf(vrow[0], vcw[5], va1);
                      accw += w0 + w1; accA = fmaf(w0, rc.x, accA); accB = fmaf(w1, rc.y, accB); }
        else { accA += rc.x; accB += rc.y; }

        rc = pair_rc2(cen1x, cen1y, cen0x, cen0y, C729, C01);
        if (BORDER) { float w0 = fmaf(vrow[0], vcw[5], va0), w1 = fmaf(vrow[0], vcw[6], va1);
                      accw += w0 + w1; accA = fmaf(w0, rc.x, accA); accB = fmaf(w1, rc.y, accB); }
        else { accA += rc.x; accB += rc.y; }

        rc = pair_rc2(b3x, b3y, cen0x, cen0y, C729, C01);
        if (BORDER) { float w0 = fmaf(vrow[0], vcw[6], va0), w1 = fmaf(vrow[0], vcw[7], va1);
                      accw += w0 + w1; accA = fmaf(w0, rc.x, accA); accB = fmaf(w1, rc.y, accB); }
        else { accA += rc.x; accB += rc.y; }

        // group 1: dx=1 (B[3]), dx=2 (A[4]), dx=3 (B[4])
        rc = pair_rc2(b3x, b3y, cen1x, cen1y, C729, C01);
        if (BORDER) { float w0 = fmaf(vrow[0], vcw[6], va2), w1 = fmaf(vrow[0], vcw[7], va3);
                      accw += w0 + w1; accC = fmaf(w0, rc.x, accC); accD = fmaf(w1, rc.y, accD); }
        else { accC += rc.x; accD += rc.y; }

        rc = pair_rc2(a4x, a4y, cen1x, cen1y, C729, C01);
        if (BORDER) { float w0 = fmaf(vrow[0], vcw[7], va2), w1 = fmaf(vrow[0], vcw[8], va3);
                      accw += w0 + w1; accC = fmaf(w0, rc.x, accC); accD = fmaf(w1, rc.y, accD); }
        else { accC += rc.x; accD += rc.y; }

        rc = pair_rc2(b4x, b4y, cen1x, cen1y, C729, C01);
        if (BORDER) { float w0 = fmaf(vrow[0], vcw[8], va2), w1 = fmaf(vrow[0], vcw[9], va3);
                      accw += w0 + w1; accC = fmaf(w0, rc.x, accC); accD = fmaf(w1, rc.y, accD); }
        else { accC += rc.x; accD += rc.y; }
    }

    // ---- dy = 1..3: j = 0..6 <-> dx = j-3 for both groups ----
    // group0: j even -> B[j/2], j odd -> A[(j+1)/2]   (offsets rel. Ab/Bb)
    // group1: same shifted +1 float4
#pragma unroll
    for (int dy = 1; dy < 4; dy++) {
        const float4* Ar = Ab + dy * PITCH;
        const float4* Br = Bb + dy * PITCH;
        ull a1x,a1y,a2x,a2y,a3x,a3y,a4x,a4y;
        ull b0x,b0y,b1x,b1y,b2x,b2y,b3x,b3y,b4x,b4y;
        lds128(Ar + 1, a1x, a1y);
        lds128(Ar + 2, a2x, a2y);
        lds128(Ar + 3, a3x, a3y);
        lds128(Ar + 4, a4x, a4y);
        lds128(Br + 0, b0x, b0y);
        lds128(Br + 1, b1x, b1y);
        lds128(Br + 2, b2x, b2y);
        lds128(Br + 3, b3x, b3y);
        lds128(Br + 4, b4x, b4y);

#pragma unroll
        for (int j = 0; j < 7; j++) {
            ull n0x, n0y, n1x, n1y;
            switch (j) {
                case 0: n0x = b0x; n0y = b0y; n1x = b1x; n1y = b1y; break;  // dx=-3
                case 1: n0x = a1x; n0y = a1y; n1x = a2x; n1y = a2y; break;  // dx=-2
                case 2: n0x = b1x; n0y = b1y; n1x = b2x; n1y = b2y; break;  // dx=-1
                case 3: n0x = a2x; n0y = a2y; n1x = a3x; n1y = a3y; break;  // dx= 0
                case 4: n0x = b2x; n0y = b2y; n1x = b3x; n1y = b3y; break;  // dx=+1
                case 5: n0x = a3x; n0y = a3y; n1x = a4x; n1y = a4y; break;  // dx=+2
                default:n0x = b3x; n0y = b3y; n1x = b4x; n1y = b4y; break;  // dx=+3
            }
            float2 rc0 = pair_rc2(n0x, n0y, cen0x, cen0y, C729, C01);
            float2 rc1 = pair_rc2(n1x, n1y, cen1x, cen1y, C729, C01);
            if (BORDER) {
                float w0 = fmaf(vrow[dy], vcw[j],     va0);
                float w1 = fmaf(vrow[dy], vcw[j + 1], va1);
                float w2 = fmaf(vrow[dy], vcw[j + 2], va2);
                float w3 = fmaf(vrow[dy], vcw[j + 3], va3);
                accw += (w0 + w1) + (w2 + w3);
                accA = fmaf(w0, rc0.x, accA);
                accB = fmaf(w1, rc0.y, accB);
                accC = fmaf(w2, rc1.x, accC);
                accD = fmaf(w3, rc1.y, accD);
            } else {
                accA += rc0.x;
                accB += rc0.y;
                accC += rc1.x;
                accD += rc1.y;
            }
        }
    }

    float s = (accA + accB) + (accC + accD);
    return BORDER ? fmaf(-0.1f, s, accw) : fmaf(-0.2f, s, 192.f);
}

__global__ __launch_bounds__(128, 8)
void census_loss_kernel(const float* __restrict__ x,
                        const float* __restrict__ y,
                        float* __restrict__ out)
{
    __shared__ __align__(16) float4 sA[NEL];
    __shared__ __align__(16) float4 sB[NEL];

    const int b    = blockIdx.z;
    const int row0 = blockIdx.y * 16;
    const int col0 = blockIdx.x * 32;
    const int tid  = threadIdx.y * 8 + threadIdx.x;

    const float2* xb2 = (const float2*)(x + (size_t)b * 3 * IMG2);
    const float2* yb2 = (const float2*)(y + (size_t)b * 3 * IMG2);

    // Pass 1: layout A. A[r][k] = pixels (col0-4+2k, col0-4+2k+1), rows row0-3+r
    const int colbase2 = (col0 - 4) >> 1;
#pragma unroll
    for (int it = 0; it < 4; it++) {
        int i = tid + it * 128;
        if (i < NEL) {
            int lr = i / PITCH;
            int k  = i - lr * PITCH;
            int gr = row0 - 3 + lr;
            int gc2 = colbase2 + k;
            float2 gx = make_float2(0.f, 0.f), gy = gx;
            if ((unsigned)gr < 256u && (unsigned)gc2 < 128u) {
                int o = gr * 128 + gc2;
                float2 a0 = xb2[o], a1 = xb2[o + 32768], a2 = xb2[o + 65536];
                float2 b0 = yb2[o], b1 = yb2[o + 32768], b2 = yb2[o + 65536];
                gx = make_float2(a0.x + a1.x + a2.x, a0.y + a1.y + a2.y);
                gy = make_float2(b0.x + b1.x + b2.x, b0.y + b1.y + b2.y);
            }
            sA[i] = make_float4(gx.x, gx.y, gy.x, gy.y);
        }
    }
    __syncthreads();

    // Pass 2: layout B (shifted +1 pixel). B[i] = {A[i].y, A[i+1].x, A[i].w, A[i+1].z}
#pragma unroll
    for (int it = 0; it < 4; it++) {
        int i = tid + it * 128;
        if (i < NEL) {
            int k = i % PITCH;
            float4 a0 = sA[i];
            float4 a1 = (k < PITCH - 1) ? sA[i + 1] : make_float4(0.f, 0.f, 0.f, 0.f);
            sB[i] = make_float4(a0.y, a1.x, a0.w, a1.z);
        }
    }
    __syncthreads();

    const int tx = threadIdx.x;          // 0..7  -> pixel cols 4tx .. 4tx+3
    const int ty = threadIdx.y;          // 0..15 -> pixel row
    const int r  = row0 + ty;
    const int C  = col0 + 4 * tx;

    // group-0 center pair at A[2tx+2] -> base offset 2tx
    const float4* Ab = sA + (ty + 3) * PITCH + 2 * tx;
    const float4* Bb = sB + (ty + 3) * PITCH + 2 * tx;

    const bool interior = (blockIdx.x - 1u < 6u) & (blockIdx.y - 1u < 14u);

    float acc = interior ? census_body<false>(Ab, Bb, r, C)
                         : census_body<true >(Ab, Bb, r, C);

    // warp + block reduction (4 warps)
#pragma unroll
    for (int s = 16; s > 0; s >>= 1)
        acc += __shfl_xor_sync(0xFFFFFFFFu, acc, s);

    __shared__ float wsum[4];
    if ((tid & 31) == 0) wsum[tid >> 5] = acc;
    __syncthreads();
    if (tid < 4) {
        float v = wsum[tid];
        v += __shfl_xor_sync(0xFu, v, 2);
        v += __shfl_xor_sync(0xFu, v, 1);
        if (tid == 0)
            atomicAdd(out, v * (1.f / 25690112.f));   // 1/(49*8*256*256)
    }
}

extern "C" void kernel_launch(void* const* d_in, const int* in_sizes, int n_in,
                              void* d_out, int out_size)
{
    const float* x = (const float*)d_in[0];
    const float* y = (const float*)d_in[1];
    float* out = (float*)d_out;

    cudaMemsetAsync(out, 0, sizeof(float));

    dim3 block(8, 16, 1);
    dim3 grid(8, 16, 8);   // 1024 blocks of 128 threads
    census_loss_kernel<<<grid, block>>>(x, y, out);
}

// round 17
// speedup vs baseline: 1.0261x; 1.0261x over previous
#include <cuda_runtime.h>

// Census loss, pair-symmetric, f32x2-packed, 2 adjacent pixels/thread.
// t = 1 - 0.1*rc, rc = 1/(0.1+e^2), e = cx-cy, c = d*rsqrt(7.29+d^2),
// d = g3(b)-g3(a), g3 = r+g+b (/3 folded into 0.81*9=7.29).
// Interior thread (48 pairs, weight 2): res = 96 - 0.2*sum(rc).
// Dual shifted float4 smem layouts (R13 core) + persistent 2-tile blocks:
// 512 blocks (single wave at 4/SM), each handles tiles by and by+8.

#define IMG   256
#define IMG2  65536
#define PITCH 20        // float4 per row (40 px: 4 left halo + 32 + 4)
#define SROWS 22        // 16 tile rows + 6 halo
#define NEL   440       // SROWS * PITCH

typedef unsigned long long ull;

__device__ __forceinline__ float frsqrt_a(float x){ float r; asm("rsqrt.approx.f32 %0, %1;" : "=f"(r) : "f"(x)); return r; }
__device__ __forceinline__ float frcp_a  (float x){ float r; asm("rcp.approx.f32 %0, %1;"   : "=f"(r) : "f"(x)); return r; }

__device__ __forceinline__ ull pk(float lo, float hi){ ull r; asm("mov.b64 %0, {%1, %2};" : "=l"(r) : "f"(lo), "f"(hi)); return r; }
__device__ __forceinline__ float2 upk(ull v){ float2 f; asm("mov.b64 {%0, %1}, %2;" : "=f"(f.x), "=f"(f.y) : "l"(v)); return f; }
__device__ __forceinline__ ull fma2(ull a, ull b, ull c){ ull r; asm("fma.rn.f32x2 %0, %1, %2, %3;" : "=l"(r) : "l"(a), "l"(b), "l"(c)); return r; }
__device__ __forceinline__ ull mul2(ull a, ull b){ ull r; asm("mul.rn.f32x2 %0, %1, %2;" : "=l"(r) : "l"(a), "l"(b)); return r; }
__device__ __forceinline__ ull sub2(ull a, ull b){ ull r; asm("sub.rn.f32x2 %0, %1, %2;" : "=l"(r) : "l"(a), "l"(b)); return r; }

// one 128-bit shared load -> x-image pair (a) and y-image pair (b)
__device__ __forceinline__ void lds128(const float4* p, ull& a, ull& b){
    asm("ld.shared.v2.b64 {%0, %1}, [%2];"
        : "=l"(a), "=l"(b) : "l"(__cvta_generic_to_shared(p)));
}

// packed rc = 1/(0.1+e^2) for two pixel-pairs (fused rational, 3 MUFU/pair)
__device__ __forceinline__ float2 pair_rc2(ull nbx, ull nby, ull cenx, ull ceny,
                                           ull C729, ull C01)
{
    ull dX = sub2(nbx, cenx);
    ull dY = sub2(nby, ceny);
    ull aX = fma2(dX, dX, C729);
    ull aY = fma2(dY, dY, C729);
    float2 a = upk(aX);
    ull rX = pk(frsqrt_a(a.x), frsqrt_a(a.y));
    float2 b = upk(aY);
    ull rY = pk(frsqrt_a(b.x), frsqrt_a(b.y));
    ull cx = mul2(dX, rX);
    ull cy = mul2(dY, rY);
    ull e  = sub2(cx, cy);
    ull dn = fma2(e, e, C01);
    float2 d = upk(dn);
    float2 rc;
    rc.x = frcp_a(d.x);
    rc.y = frcp_a(d.y);
    return rc;
}

template<bool BORDER>
__device__ __forceinline__ float census_body(const float4* __restrict__ Ab,
                                             const float4* __restrict__ Bb,
                                             int r, int c0)
{
    const ull C729 = pk(7.29f, 7.29f);
    const ull C01  = pk(0.1f, 0.1f);

    float vrow[4], vcw[8];
    float va0 = 0.f, va1 = 0.f;
    if (BORDER) {
#pragma unroll
        for (int d = 0; d < 4; d++) vrow[d] = ((unsigned)(r + d - 3) < 250u) ? 1.f : 0.f;   // valid(row r+d)
#pragma unroll
        for (int j = 0; j < 8; j++) vcw[j] = ((unsigned)(c0 - 6 + j) < 250u) ? 1.f : 0.f;   // valid(col c0+j-3)
        va0 = vrow[0] * vcw[3];
        va1 = vrow[0] * vcw[4];
    }

    float accA = 0.f, accB = 0.f, accw = 0.f;

    ull cenx, ceny;
    lds128(Ab + 2, cenx, ceny);

    // ---- dy = 0: dx = 1 (B[2]), dx = 2 (A[3]), dx = 3 (B[3]) ----
    {
        ull nbx, nby;
        lds128(Bb + 2, nbx, nby);
        float2 rc = pair_rc2(nbx, nby, cenx, ceny, C729, C01);
        if (BORDER) { float w0 = fmaf(vrow[0], vcw[4], va0), w1 = fmaf(vrow[0], vcw[5], va1);
                      accw += w0 + w1; accA = fmaf(w0, rc.x, accA); accB = fmaf(w1, rc.y, accB); }
        else { accA += rc.x; accB += rc.y; }

        lds128(Ab + 3, nbx, nby);
        rc = pair_rc2(nbx, nby, cenx, ceny, C729, C01);
        if (BORDER) { float w0 = fmaf(vrow[0], vcw[5], va0), w1 = fmaf(vrow[0], vcw[6], va1);
                      accw += w0 + w1; accA = fmaf(w0, rc.x, accA); accB = fmaf(w1, rc.y, accB); }
        else { accA += rc.x; accB += rc.y; }

        lds128(Bb + 3, nbx, nby);
        rc = pair_rc2(nbx, nby, cenx, ceny, C729, C01);
        if (BORDER) { float w0 = fmaf(vrow[0], vcw[6], va0), w1 = fmaf(vrow[0], vcw[7], va1);
                      accw += w0 + w1; accA = fmaf(w0, rc.x, accA); accB = fmaf(w1, rc.y, accB); }
        else { accA += rc.x; accB += rc.y; }
    }

    // ---- dy = 1..3: j = 0..6 <-> dx = j-3 ----
    // j even -> B[j/2], j odd -> A[(j+1)/2]   (offsets rel. Ab/Bb)
#pragma unroll
    for (int dy = 1; dy < 4; dy++) {
        const float4* Ar = Ab + dy * PITCH;
        const float4* Br = Bb + dy * PITCH;
#pragma unroll
        for (int j = 0; j < 7; j++) {
            ull nbx, nby;
            if (j & 1) lds128(Ar + ((j + 1) >> 1), nbx, nby);
            else       lds128(Br + (j >> 1),       nbx, nby);
            float2 rc = pair_rc2(nbx, nby, cenx, ceny, C729, C01);
            if (BORDER) {
                float w0 = fmaf(vrow[dy], vcw[j], va0);
                float w1 = fmaf(vrow[dy], vcw[j + 1], va1);
                accw += w0 + w1;
                accA = fmaf(w0, rc.x, accA);
                accB = fmaf(w1, rc.y, accB);
            } else {
                accA += rc.x;
                accB += rc.y;
            }
        }
    }

    float s = accA + accB;
    return BORDER ? fmaf(-0.1f, s, accw) : fmaf(-0.2f, s, 96.f);
}

__global__ __launch_bounds__(256, 4)
void census_loss_kernel(const float* __restrict__ x,
                        const float* __restrict__ y,
                        float* __restrict__ out)
{
    __shared__ __align__(16) float4 sA[NEL];
    __shared__ __align__(16) float4 sB[NEL];

    const int b    = blockIdx.z;
    const int col0 = blockIdx.x * 32;
    const int tid  = threadIdx.y * 16 + threadIdx.x;
    const int tx   = threadIdx.x;        // 0..15 -> pixel cols 2tx, 2tx+1
    const int ty   = threadIdx.y;        // 0..15 -> pixel row

    const float2* xb2 = (const float2*)(x + (size_t)b * 3 * IMG2);
    const float2* yb2 = (const float2*)(y + (size_t)b * 3 * IMG2);
    const int colbase2 = (col0 - 4) >> 1;   // gmem float2 col index of A[.][0]

    float acc = 0.f;

#pragma unroll 1
    for (int k = 0; k < 2; k++) {
        const int by   = blockIdx.y + 8 * k;   // tile row-group 0..15
        const int row0 = by * 16;

        __syncthreads();   // previous-iteration readers done before overwrite

        // Pass 1: layout A. A[r][kk] = pixels (col0-4+2kk, ...), rows row0-3+r
        float4 own0, own1;
#pragma unroll
        for (int it = 0; it < 2; it++) {
            int i = tid + it * 256;
            if (i < NEL) {
                int lr  = i / PITCH;
                int kk  = i - lr * PITCH;
                int gr  = row0 - 3 + lr;
                int gc2 = colbase2 + kk;
                float2 gx = make_float2(0.f, 0.f), gy = gx;
                if ((unsigned)gr < 256u && (unsigned)gc2 < 128u) {
                    int o = gr * 128 + gc2;
                    float2 a0 = xb2[o], a1 = xb2[o + 32768], a2 = xb2[o + 65536];
                    float2 b0 = yb2[o], b1 = yb2[o + 32768], b2 = yb2[o + 65536];
                    gx = make_float2(a0.x + a1.x + a2.x, a0.y + a1.y + a2.y);
                    gy = make_float2(b0.x + b1.x + b2.x, b0.y + b1.y + b2.y);
                }
                float4 v = make_float4(gx.x, gx.y, gy.x, gy.y);
                sA[i] = v;
                if (it == 0) own0 = v; else own1 = v;
            }
        }
        __syncthreads();

        // Pass 2: layout B (shifted +1 px). B[i] = {A[i].y, A[i+1].x, A[i].w, A[i+1].z}
        // own element comes from registers; only the +1 neighbor is re-loaded.
#pragma unroll
        for (int it = 0; it < 2; it++) {
            int i = tid + it * 256;
            if (i < NEL) {
                int kk = i % PITCH;
                float4 a0 = (it == 0) ? own0 : own1;
                float4 a1 = (kk < PITCH - 1) ? sA[i + 1] : make_float4(0.f, 0.f, 0.f, 0.f);
                sB[i] = make_float4(a0.y, a1.x, a0.w, a1.z);
            }
        }
        __syncthreads();

        const int r  = row0 + ty;
        const int c0 = col0 + 2 * tx;

        const float4* Ab = sA + (ty + 3) * PITCH + tx;
        const float4* Bb = sB + (ty + 3) * PITCH + tx;

        const bool interior = (blockIdx.x - 1u < 6u) & (by - 1u < 14u);

        acc += interior ? census_body<false>(Ab, Bb, r, c0)
                        : census_body<true >(Ab, Bb, r, c0);
    }

    // warp + block reduction
#pragma unroll
    for (int s = 16; s > 0; s >>= 1)
        acc += __shfl_xor_sync(0xFFFFFFFFu, acc, s);

    __shared__ float wsum[8];
    if ((tid & 31) == 0) wsum[tid >> 5] = acc;
    __syncthreads();
    if (tid < 8) {
        float v = wsum[tid];
        v += __shfl_xor_sync(0xFFu, v, 4);
        v += __shfl_xor_sync(0xFFu, v, 2);
        v += __shfl_xor_sync(0xFFu, v, 1);
        if (tid == 0)
            atomicAdd(out, v * (1.f / 25690112.f));   // 1/(49*8*256*256)
    }
}

extern "C" void kernel_launch(void* const* d_in, const int* in_sizes, int n_in,
                              void* d_out, int out_size)
{
    const float* x = (const float*)d_in[0];
    const float* y = (const float*)d_in[1];
    float* out = (float*)d_out;

    cudaMemsetAsync(out, 0, sizeof(float));

    dim3 block(16, 16, 1);
    dim3 grid(8, 8, 8);   // 512 persistent blocks, 2 tiles each -> single wave
    census_loss_kernel<<<grid, block>>>(x, y, out);
}